// round 14
// baseline (speedup 1.0000x reference)
#include <cuda_runtime.h>

// Problem constants (B=1 fixed)
#define D_   24
#define H_   96
#define W_   96
#define C_   32
#define HW_  (H_*W_)          // 9216
#define S_   (D_*HW_)         // 221184
#define TOT_ (C_*S_)          // 7077888
#define OC_  54               // offset conv output channels
#define OCP_ 56               // padded
#define G_   4
#define CPG_ (C_/G_)
#define NPG_ (CPG_*S_)
#define STAT_BLOCKS 64

typedef unsigned long long u64;

// packed f32x2 FMA: d.lo += a.lo*b.lo ; d.hi += a.hi*b.hi  (2x FP32 rate)
#define FFMA2(d, a, b) \
    asm("fma.rn.f32x2 %0, %1, %2, %0;" : "+l"(d) : "l"(a), "l"(b))
#define PACK2(d, x) \
    asm("mov.b64 %0, {%1, %1};" : "=l"(d) : "r"(__float_as_uint(x)))

#define CP_ASYNC16(dst_u32, src_ptr) \
    asm volatile("cp.async.cg.shared.global [%0], [%1], 16;" :: "r"(dst_u32), "l"(src_ptr))
#define CP_COMMIT() asm volatile("cp.async.commit_group;")
#define CP_WAIT1()  asm volatile("cp.async.wait_group 1;")

static __device__ __forceinline__ float2 unpk(u64 v) {
    unsigned int lo, hi;
    asm("mov.b64 {%0, %1}, %2;" : "=r"(lo), "=r"(hi) : "l"(v));
    float2 r; r.x = __uint_as_float(lo); r.y = __uint_as_float(hi);
    return r;
}
static __device__ __forceinline__ unsigned int smem_u32(const void* p) {
    unsigned int a;
    asm("{ .reg .u64 t; cvta.to.shared.u64 t, %1; cvt.u32.u64 %0, t; }" : "=r"(a) : "l"(p));
    return a;
}

// Scratch (device globals: allocation-free, graph-capture safe)
__device__ float g_h[TOT_];          // gn+relu output, [c][s] (conv input)
__device__ float g_hT[TOT_];         // gn+relu output, [s][c] (deform gather input)
__device__ float g_t[TOT_];          // pass-1 result [c][s]
__device__ float g_offb[OC_*S_];
__device__ float g_part[G_*STAT_BLOCKS*2];
__device__ float g_ms[G_*2];
__device__ float g_cw[27*C_*OCP_];   // transposed conv weights [tap][c][oc56]
__device__ float g_dw[27*C_*C_];     // transposed deform weights [tap][c][oc32]

// ---------------------------------------------------------------------------
__global__ void prep_cw(const float* __restrict__ ow, float* __restrict__ cw) {
    int idx = blockIdx.x * 256 + threadIdx.x;        // 48384
    if (idx >= 27*C_*OCP_) return;
    int oc  = idx % OCP_;
    int c   = (idx / OCP_) % C_;
    int tap = idx / (OCP_*C_);
    cw[idx] = (oc < OC_) ? ow[(oc*C_ + c)*27 + tap] : 0.f;
}
__global__ void prep_dw(const float* __restrict__ dw, float* __restrict__ dwr) {
    int idx = blockIdx.x * 256 + threadIdx.x;        // 27648
    if (idx >= 27*C_*C_) return;
    int oc  = idx & 31;
    int c   = (idx >> 5) & 31;
    int tap = idx >> 10;
    dwr[idx] = dw[(oc*C_ + c)*27 + tap];
}

// ---------------------------------------------------------------------------
// Transpose [c][s] -> [s][c] (tiled, conflict-free)
// ---------------------------------------------------------------------------
__global__ void __launch_bounds__(256)
transpose_cs(const float* __restrict__ in, float* __restrict__ outT) {
    __shared__ float t[32][33];
    int s0 = blockIdx.x * 32;
    int tx = threadIdx.x & 31, ty = threadIdx.x >> 5;   // ty 0..7
    #pragma unroll
    for (int i = 0; i < 4; ++i) {
        int c = ty + 8*i;
        t[c][tx] = in[c * S_ + s0 + tx];
    }
    __syncthreads();
    #pragma unroll
    for (int i = 0; i < 4; ++i) {
        int sl = ty + 8*i;
        outT[(size_t)(s0 + sl) * C_ + tx] = t[tx][sl];
    }
}

// ---------------------------------------------------------------------------
// GroupNorm (unchanged, known good)
// ---------------------------------------------------------------------------
__global__ void gn_stats(const float* __restrict__ in) {
    int g = blockIdx.y;
    const float4* p = (const float4*)(in + (size_t)g * NPG_);
    const int n4 = NPG_ / 4;
    float s = 0.f, q = 0.f;
    for (int i = blockIdx.x * blockDim.x + threadIdx.x; i < n4; i += STAT_BLOCKS * 256) {
        float4 v = p[i];
        s += v.x + v.y + v.z + v.w;
        q += v.x*v.x + v.y*v.y + v.z*v.z + v.w*v.w;
    }
    __shared__ float sh[512];
    int t = threadIdx.x;
    sh[t] = s; sh[256 + t] = q;
    __syncthreads();
    for (int o = 128; o > 0; o >>= 1) {
        if (t < o) { sh[t] += sh[t + o]; sh[256 + t] += sh[256 + t + o]; }
        __syncthreads();
    }
    if (t == 0) {
        g_part[(g*STAT_BLOCKS + blockIdx.x)*2 + 0] = sh[0];
        g_part[(g*STAT_BLOCKS + blockIdx.x)*2 + 1] = sh[256];
    }
}

__global__ void gn_fin() {
    int g = blockIdx.x, t = threadIdx.x;
    __shared__ float a[64], b[64];
    a[t] = g_part[(g*STAT_BLOCKS + t)*2 + 0];
    b[t] = g_part[(g*STAT_BLOCKS + t)*2 + 1];
    __syncthreads();
    for (int o = 32; o > 0; o >>= 1) {
        if (t < o) { a[t] += a[t + o]; b[t] += b[t + o]; }
        __syncthreads();
    }
    if (t == 0) {
        float mean = a[0] / (float)NPG_;
        float var  = b[0] / (float)NPG_ - mean * mean;
        g_ms[g*2 + 0] = mean;
        g_ms[g*2 + 1] = rsqrtf(var + 1e-5f);
    }
}

__global__ void gn_apply(const float* __restrict__ in, const float* __restrict__ gamma,
                         const float* __restrict__ beta, float* __restrict__ out) {
    int i4 = blockIdx.x * blockDim.x + threadIdx.x;
    int c  = i4 / (S_ / 4);
    int g  = c >> 3;
    float mean = g_ms[g*2 + 0], rstd = g_ms[g*2 + 1];
    float sc = rstd * gamma[c];
    float sb = beta[c] - mean * sc;
    float4 v = ((const float4*)in)[i4];
    float4 r;
    r.x = fmaxf(fmaf(v.x, sc, sb), 0.f);
    r.y = fmaxf(fmaf(v.y, sc, sb), 0.f);
    r.z = fmaxf(fmaf(v.z, sc, sb), 0.f);
    r.w = fmaxf(fmaf(v.w, sc, sb), 0.f);
    ((float4*)out)[i4] = r;
}

// ---------------------------------------------------------------------------
// Offset conv, R6 tile shape + cp.async double-buffered staging (R11, known good).
// ---------------------------------------------------------------------------
#define INP_ 104
#define SMEM_CONV ((2*C_*INP_ + 2*3*C_*OCP_) * 4)    // 69632 bytes
__global__ void __launch_bounds__(224)
conv_gemm(const float* __restrict__ in, const float* __restrict__ cw,
          const float* __restrict__ bias, float* __restrict__ out) {
    extern __shared__ __align__(16) float smem[];
    float* s_in = smem;                         // 2 x C_ x INP_
    float* s_w  = smem + 2 * C_ * INP_;         // 2 x 3*C_*OCP_
    unsigned int sin_a = smem_u32(s_in);
    unsigned int sw_a  = smem_u32(s_w);

    int vg = threadIdx.x & 31;
    int og = threadIdx.x >> 5;
    int d  = blockIdx.x;
    int h  = blockIdx.y;

    for (int i = threadIdx.x; i < 2 * C_; i += 224) {
        s_in[i * INP_ + 3]   = 0.f;
        s_in[i * INP_ + 100] = 0.f;
    }

    u64 acc[12];
    #pragma unroll
    for (int i = 0; i < 12; i++) acc[i] = 0ull;

    {
        int zd = d - 1, zh = h - 1;
        if ((unsigned)zd < D_ && (unsigned)zh < H_) {
            const float* rb = in + zd * HW_ + zh * W_;
            for (int idx = threadIdx.x; idx < C_ * 24; idx += 224) {
                int c = idx / 24, q = idx - c * 24;
                CP_ASYNC16(sin_a + (c * INP_ + 4 + 4*q) * 4, rb + c * S_ + 4*q);
            }
            const float* wb = cw;
            for (int idx = threadIdx.x; idx < (3*C_*OCP_)/4; idx += 224)
                CP_ASYNC16(sw_a + idx * 16, wb + 4*idx);
        }
    }
    CP_COMMIT();

    #pragma unroll 1
    for (int p = 0; p < 9; ++p) {
        if (p < 8) {
            int pn = p + 1;
            int ti = pn / 3, tj = pn - 3 * ti;
            int zd = d + ti - 1, zh = h + tj - 1;
            if ((unsigned)zd < D_ && (unsigned)zh < H_) {
                int b = pn & 1;
                const float* rb = in + zd * HW_ + zh * W_;
                unsigned int din = sin_a + (b * C_ * INP_) * 4;
                for (int idx = threadIdx.x; idx < C_ * 24; idx += 224) {
                    int c = idx / 24, q = idx - c * 24;
                    CP_ASYNC16(din + (c * INP_ + 4 + 4*q) * 4, rb + c * S_ + 4*q);
                }
                const float* wb = cw + pn * 3 * (C_ * OCP_);
                unsigned int dw = sw_a + (b * 3 * C_ * OCP_) * 4;
                for (int idx = threadIdx.x; idx < (3*C_*OCP_)/4; idx += 224)
                    CP_ASYNC16(dw + idx * 16, wb + 4*idx);
            }
        }
        CP_COMMIT();
        CP_WAIT1();
        __syncthreads();

        int ti = p / 3, tj = p - 3 * ti;
        int zd = d + ti - 1, zh = h + tj - 1;
        if ((unsigned)zd < D_ && (unsigned)zh < H_) {
            const float* bin = s_in + (p & 1) * C_ * INP_;
            const float* bw  = s_w  + (p & 1) * 3 * C_ * OCP_;

            #pragma unroll 2
            for (int c = 0; c < C_; ++c) {
                const float* sr = bin + c * INP_ + 3 * vg + 3;
                u64 pv[5];
                #pragma unroll
                for (int t = 0; t < 5; ++t) { PACK2(pv[t], sr[t]); }
                #pragma unroll
                for (int tk = 0; tk < 3; ++tk) {
                    const ulonglong2* wq =
                        (const ulonglong2*)(bw + (tk * C_ + c) * OCP_ + og * 8);
                    ulonglong2 w0 = wq[0];
                    ulonglong2 w1 = wq[1];
                    #pragma unroll
                    for (int v = 0; v < 3; ++v) {
                        u64 b = pv[tk + v];
                        FFMA2(acc[v*4 + 0], w0.x, b);
                        FFMA2(acc[v*4 + 1], w0.y, b);
                        FFMA2(acc[v*4 + 2], w1.x, b);
                        FFMA2(acc[v*4 + 3], w1.y, b);
                    }
                }
            }
        }
        __syncthreads();
    }

    int sprow = (d * H_ + h) * W_ + 3 * vg;
    #pragma unroll
    for (int p = 0; p < 4; ++p) {
        int oc = og * 8 + 2 * p;
        if (oc < OC_) {
            float bx = __ldg(bias + oc);
            float by = __ldg(bias + oc + 1);
            #pragma unroll
            for (int v = 0; v < 3; ++v) {
                float2 a = unpk(acc[v*4 + p]);
                out[(oc+0) * S_ + sprow + v] = a.x + bx;
                out[(oc+1) * S_ + sprow + v] = a.y + by;
            }
        }
    }
}

// ---------------------------------------------------------------------------
// Deformable conv with CHANNEL-LAST gather input (g_hT, [s][c]).
// Per (tap, 4-channel group): 4x LDG.128 (one per bilinear corner, 4 channels
// each) instead of 16 scattered LDG.32. 1 voxel/thread, 32 ocs packed,
// per-ti 9-tap weight slab (R9). Output stays [c][s].
// ---------------------------------------------------------------------------
__global__ void __launch_bounds__(256)
deform(const float* __restrict__ inT, const float* __restrict__ offs,
       const float* __restrict__ dwt, const float* __restrict__ bias,
       const float* __restrict__ resid, float* __restrict__ out) {
    __shared__ __align__(16) float ws[9 * C_ * C_];   // 36 KB
    int sp = blockIdx.x * 256 + threadIdx.x;
    int d = sp / HW_;              // uniform across block
    int r = sp - d * HW_;
    int h = r / W_;
    int w = r - h * W_;

    u64 acc[16];
    #pragma unroll
    for (int i = 0; i < 16; i++) acc[i] = 0ull;

    #pragma unroll 1
    for (int ti = 0; ti < 3; ++ti) {
        __syncthreads();
        {
            const float4* src = (const float4*)(dwt + ti * (9 * C_ * C_));
            float4* dst = (float4*)ws;
            for (int idx = threadIdx.x; idx < 9 * C_ * C_ / 4; idx += 256)
                dst[idx] = src[idx];
        }
        __syncthreads();
        int zd = d + ti - 1;
        if ((unsigned)zd >= D_) continue;             // uniform per block
        const float* baseT = inT + (size_t)zd * HW_ * C_;

        #pragma unroll 1
        for (int tl = 0; tl < 9; ++tl) {              // tj*3+tk
            int tj = tl / 3, tk = tl - 3 * tj;
            int tap = ti * 9 + tl;

            float offh = offs[(2*tap + 0) * S_ + sp];
            float offw = offs[(2*tap + 1) * S_ + sp];
            float hp = (float)(h + tj - 1) + offh;
            float wp = (float)(w + tk - 1) + offw;
            float h0f = floorf(hp), w0f = floorf(wp);
            int h0 = (int)h0f, w0 = (int)w0f;
            float lh = hp - h0f, lw = wp - w0f;

            float m00 = ((unsigned)h0     < H_ && (unsigned)w0     < W_) ? 1.f : 0.f;
            float m01 = ((unsigned)h0     < H_ && (unsigned)(w0+1) < W_) ? 1.f : 0.f;
            float m10 = ((unsigned)(h0+1) < H_ && (unsigned)w0     < W_) ? 1.f : 0.f;
            float m11 = ((unsigned)(h0+1) < H_ && (unsigned)(w0+1) < W_) ? 1.f : 0.f;
            float w00 = (1.f - lh) * (1.f - lw) * m00;
            float w01 = (1.f - lh) * lw         * m01;
            float w10 = lh         * (1.f - lw) * m10;
            float w11 = lh         * lw         * m11;

            int h0c = min(max(h0,     0), H_ - 1);
            int h1c = min(max(h0 + 1, 0), H_ - 1);
            int w0c = min(max(w0,     0), W_ - 1);
            int w1c = min(max(w0 + 1, 0), W_ - 1);
            const float4* p00 = (const float4*)(baseT + (size_t)(h0c * W_ + w0c) * C_);
            const float4* p01 = (const float4*)(baseT + (size_t)(h0c * W_ + w1c) * C_);
            const float4* p10 = (const float4*)(baseT + (size_t)(h1c * W_ + w0c) * C_);
            const float4* p11 = (const float4*)(baseT + (size_t)(h1c * W_ + w1c) * C_);

            const float* wp_s = ws + tl * (C_ * C_);
            #pragma unroll 2
            for (int cq = 0; cq < 8; ++cq) {          // 4 channels per iter
                float4 a00 = __ldg(p00 + cq);
                float4 a01 = __ldg(p01 + cq);
                float4 a10 = __ldg(p10 + cq);
                float4 a11 = __ldg(p11 + cq);
                float v0 = w00*a00.x + w01*a01.x + w10*a10.x + w11*a11.x;
                float v1 = w00*a00.y + w01*a01.y + w10*a10.y + w11*a11.y;
                float v2 = w00*a00.z + w01*a01.z + w10*a10.z + w11*a11.z;
                float v3 = w00*a00.w + w01*a01.w + w10*a10.w + w11*a11.w;
                u64 b0, b1, b2, b3;
                PACK2(b0, v0); PACK2(b1, v1); PACK2(b2, v2); PACK2(b3, v3);
                const ulonglong2* wq0 = (const ulonglong2*)(wp_s + (4*cq + 0) * C_);
                const ulonglong2* wq1 = (const ulonglong2*)(wp_s + (4*cq + 1) * C_);
                const ulonglong2* wq2 = (const ulonglong2*)(wp_s + (4*cq + 2) * C_);
                const ulonglong2* wq3 = (const ulonglong2*)(wp_s + (4*cq + 3) * C_);
                #pragma unroll
                for (int q = 0; q < 8; ++q) {
                    ulonglong2 t0 = wq0[q];
                    FFMA2(acc[2*q + 0], t0.x, b0);
                    FFMA2(acc[2*q + 1], t0.y, b0);
                }
                #pragma unroll
                for (int q = 0; q < 8; ++q) {
                    ulonglong2 t1 = wq1[q];
                    FFMA2(acc[2*q + 0], t1.x, b1);
                    FFMA2(acc[2*q + 1], t1.y, b1);
                }
                #pragma unroll
                for (int q = 0; q < 8; ++q) {
                    ulonglong2 t2 = wq2[q];
                    FFMA2(acc[2*q + 0], t2.x, b2);
                    FFMA2(acc[2*q + 1], t2.y, b2);
                }
                #pragma unroll
                for (int q = 0; q < 8; ++q) {
                    ulonglong2 t3 = wq3[q];
                    FFMA2(acc[2*q + 0], t3.x, b3);
                    FFMA2(acc[2*q + 1], t3.y, b3);
                }
            }
        }
    }

    if (resid) {
        #pragma unroll
        for (int q = 0; q < 16; ++q) {
            int oc = 2 * q;
            float2 a = unpk(acc[q]);
            int i0 = (oc+0) * S_ + sp, i1 = (oc+1) * S_ + sp;
            out[i0] = a.x + __ldg(bias + oc)     + __ldg(resid + i0);
            out[i1] = a.y + __ldg(bias + oc + 1) + __ldg(resid + i1);
        }
    } else {
        #pragma unroll
        for (int q = 0; q < 16; ++q) {
            int oc = 2 * q;
            float2 a = unpk(acc[q]);
            out[(oc+0) * S_ + sp] = a.x + __ldg(bias + oc);
            out[(oc+1) * S_ + sp] = a.y + __ldg(bias + oc + 1);
        }
    }
}

// ---------------------------------------------------------------------------
extern "C" void kernel_launch(void* const* d_in, const int* in_sizes, int n_in,
                              void* d_out, int out_size) {
    const float* x   = (const float*)d_in[0];
    const float* g1  = (const float*)d_in[1];
    const float* be1 = (const float*)d_in[2];
    const float* g2  = (const float*)d_in[3];
    const float* be2 = (const float*)d_in[4];
    const float* ow1 = (const float*)d_in[5];
    const float* ob1 = (const float*)d_in[6];
    const float* dw1 = (const float*)d_in[7];
    const float* db1 = (const float*)d_in[8];
    const float* ow2 = (const float*)d_in[9];
    const float* ob2 = (const float*)d_in[10];
    const float* dw2 = (const float*)d_in[11];
    const float* db2 = (const float*)d_in[12];
    float* out = (float*)d_out;

    float *ph, *phT, *pt, *poff, *pcw, *pdw;
    cudaGetSymbolAddress((void**)&ph,   g_h);
    cudaGetSymbolAddress((void**)&phT,  g_hT);
    cudaGetSymbolAddress((void**)&pt,   g_t);
    cudaGetSymbolAddress((void**)&poff, g_offb);
    cudaGetSymbolAddress((void**)&pcw,  g_cw);
    cudaGetSymbolAddress((void**)&pdw,  g_dw);

    cudaFuncSetAttribute(conv_gemm,
        cudaFuncAttributeMaxDynamicSharedMemorySize, SMEM_CONV);

    dim3 sg(STAT_BLOCKS, G_);
    const int NB_GN = TOT_ / 4 / 256;
    const int NB_SP = S_ / 256;      // 864
    const int NB_TR = S_ / 32;       // 6912
    dim3 gc(D_, H_);

    // pass 1
    prep_cw<<<(27*C_*OCP_ + 255)/256, 256>>>(ow1, pcw);
    prep_dw<<<(27*C_*C_  + 255)/256, 256>>>(dw1, pdw);
    gn_stats<<<sg, 256>>>(x);
    gn_fin<<<G_, 64>>>();
    gn_apply<<<NB_GN, 256>>>(x, g1, be1, ph);
    transpose_cs<<<NB_TR, 256>>>(ph, phT);
    conv_gemm<<<gc, 224, SMEM_CONV>>>(ph, pcw, ob1, poff);
    deform<<<NB_SP, 256>>>(phT, poff, pdw, db1, nullptr, pt);

    // pass 2 (+ residual into d_out)
    prep_cw<<<(27*C_*OCP_ + 255)/256, 256>>>(ow2, pcw);
    prep_dw<<<(27*C_*C_  + 255)/256, 256>>>(dw2, pdw);
    gn_stats<<<sg, 256>>>(pt);
    gn_fin<<<G_, 64>>>();
    gn_apply<<<NB_GN, 256>>>(pt, g2, be2, ph);
    transpose_cs<<<NB_TR, 256>>>(ph, phT);
    conv_gemm<<<gc, 224, SMEM_CONV>>>(ph, pcw, ob2, poff);
    deform<<<NB_SP, 256>>>(phT, poff, pdw, db2, x, out);
}

// round 15
// speedup vs baseline: 1.4015x; 1.4015x over previous
#include <cuda_runtime.h>

// Problem constants (B=1 fixed)
#define D_   24
#define H_   96
#define W_   96
#define C_   32
#define HW_  (H_*W_)          // 9216
#define S_   (D_*HW_)         // 221184
#define TOT_ (C_*S_)          // 7077888
#define OC_  54               // offset conv output channels
#define OCP_ 56               // padded
#define G_   4
#define CPG_ (C_/G_)
#define NPG_ (CPG_*S_)
#define STAT_BLOCKS 64

typedef unsigned long long u64;

// packed f32x2 FMA: d.lo += a.lo*b.lo ; d.hi += a.hi*b.hi  (2x FP32 rate)
#define FFMA2(d, a, b) \
    asm("fma.rn.f32x2 %0, %1, %2, %0;" : "+l"(d) : "l"(a), "l"(b))
#define PACK2(d, x) \
    asm("mov.b64 %0, {%1, %1};" : "=l"(d) : "r"(__float_as_uint(x)))

#define CP_ASYNC16(dst_u32, src_ptr) \
    asm volatile("cp.async.cg.shared.global [%0], [%1], 16;" :: "r"(dst_u32), "l"(src_ptr))
#define CP_COMMIT() asm volatile("cp.async.commit_group;")
#define CP_WAIT1()  asm volatile("cp.async.wait_group 1;")

static __device__ __forceinline__ float2 unpk(u64 v) {
    unsigned int lo, hi;
    asm("mov.b64 {%0, %1}, %2;" : "=r"(lo), "=r"(hi) : "l"(v));
    float2 r; r.x = __uint_as_float(lo); r.y = __uint_as_float(hi);
    return r;
}
static __device__ __forceinline__ unsigned int smem_u32(const void* p) {
    unsigned int a;
    asm("{ .reg .u64 t; cvta.to.shared.u64 t, %1; cvt.u32.u64 %0, t; }" : "=r"(a) : "l"(p));
    return a;
}

// Scratch (device globals: allocation-free, graph-capture safe)
__device__ float g_h[TOT_];          // gn+relu output [c][s]
__device__ float g_t[TOT_];          // pass-1 result
__device__ float g_offb[OC_*S_];
__device__ float g_part[G_*STAT_BLOCKS*2];
__device__ float g_cw[27*C_*OCP_];   // transposed conv weights [tap][c][oc56]
__device__ float g_dw[27*C_*C_];     // transposed deform weights [tap][c][oc32]

// ---------------------------------------------------------------------------
// K1: GroupNorm partial stats + (fused) both weight transposes.
// Grid (STAT_BLOCKS, G_) x 256 threads = 65536 threads; prep work is
// distributed over flat thread ids (76032 elements total).
// ---------------------------------------------------------------------------
__global__ void gn_stats_prep(const float* __restrict__ in,
                              const float* __restrict__ ow,
                              const float* __restrict__ dwi) {
    // ---- fused weight preps (pass-specific weights) ----
    {
        int flat = (blockIdx.y * STAT_BLOCKS + blockIdx.x) * 256 + threadIdx.x;
        if (flat < 27*C_*OCP_) {               // 48384
            int oc  = flat % OCP_;
            int c   = (flat / OCP_) % C_;
            int tap = flat / (OCP_*C_);
            g_cw[flat] = (oc < OC_) ? ow[(oc*C_ + c)*27 + tap] : 0.f;
        }
        if (flat < 27*C_*C_) {                 // 27648
            int oc  = flat & 31;
            int c   = (flat >> 5) & 31;
            int tap = flat >> 10;
            g_dw[flat] = dwi[(oc*C_ + c)*27 + tap];
        }
    }
    // ---- stats ----
    int g = blockIdx.y;
    const float4* p = (const float4*)(in + (size_t)g * NPG_);
    const int n4 = NPG_ / 4;
    float s = 0.f, q = 0.f;
    for (int i = blockIdx.x * blockDim.x + threadIdx.x; i < n4; i += STAT_BLOCKS * 256) {
        float4 v = p[i];
        s += v.x + v.y + v.z + v.w;
        q += v.x*v.x + v.y*v.y + v.z*v.z + v.w*v.w;
    }
    __shared__ float sh[512];
    int t = threadIdx.x;
    sh[t] = s; sh[256 + t] = q;
    __syncthreads();
    for (int o = 128; o > 0; o >>= 1) {
        if (t < o) { sh[t] += sh[t + o]; sh[256 + t] += sh[256 + t + o]; }
        __syncthreads();
    }
    if (t == 0) {
        g_part[(g*STAT_BLOCKS + blockIdx.x)*2 + 0] = sh[0];
        g_part[(g*STAT_BLOCKS + blockIdx.x)*2 + 1] = sh[256];
    }
}

// ---------------------------------------------------------------------------
// K2: gn_apply with fused final reduction (each block redundantly reduces
// its group's 64 partials — deterministic, identical result to gn_fin).
// ---------------------------------------------------------------------------
__global__ void gn_apply_fin(const float* __restrict__ in, const float* __restrict__ gamma,
                             const float* __restrict__ beta, float* __restrict__ out) {
    int i4 = blockIdx.x * blockDim.x + threadIdx.x;
    int c  = i4 / (S_ / 4);            // uniform per block (55296 % 256 == 0)
    int g  = c >> 3;

    __shared__ float red[128];
    int t = threadIdx.x;
    if (t < 64) {
        red[t]      = g_part[(g*STAT_BLOCKS + t)*2 + 0];
        red[64 + t] = g_part[(g*STAT_BLOCKS + t)*2 + 1];
    }
    __syncthreads();
    for (int o = 32; o > 0; o >>= 1) {
        if (t < o) { red[t] += red[t + o]; red[64 + t] += red[64 + t + o]; }
        __syncthreads();
    }
    float mean = red[0] / (float)NPG_;
    float var  = red[64] / (float)NPG_ - mean * mean;
    float rstd = rsqrtf(var + 1e-5f);

    float sc = rstd * gamma[c];
    float sb = beta[c] - mean * sc;
    float4 v = ((const float4*)in)[i4];
    float4 r;
    r.x = fmaxf(fmaf(v.x, sc, sb), 0.f);
    r.y = fmaxf(fmaf(v.y, sc, sb), 0.f);
    r.z = fmaxf(fmaf(v.z, sc, sb), 0.f);
    r.w = fmaxf(fmaf(v.w, sc, sb), 0.f);
    ((float4*)out)[i4] = r;
}

// ---------------------------------------------------------------------------
// K3: Offset conv, R6 tile + cp.async double-buffered staging (R11 verbatim).
// ---------------------------------------------------------------------------
#define INP_ 104
#define SMEM_CONV ((2*C_*INP_ + 2*3*C_*OCP_) * 4)    // 69632 bytes
__global__ void __launch_bounds__(224)
conv_gemm(const float* __restrict__ in, const float* __restrict__ cw,
          const float* __restrict__ bias, float* __restrict__ out) {
    extern __shared__ __align__(16) float smem[];
    float* s_in = smem;                         // 2 x C_ x INP_
    float* s_w  = smem + 2 * C_ * INP_;         // 2 x 3*C_*OCP_
    unsigned int sin_a = smem_u32(s_in);
    unsigned int sw_a  = smem_u32(s_w);

    int vg = threadIdx.x & 31;
    int og = threadIdx.x >> 5;
    int d  = blockIdx.x;
    int h  = blockIdx.y;

    for (int i = threadIdx.x; i < 2 * C_; i += 224) {
        s_in[i * INP_ + 3]   = 0.f;
        s_in[i * INP_ + 100] = 0.f;
    }

    u64 acc[12];
    #pragma unroll
    for (int i = 0; i < 12; i++) acc[i] = 0ull;

    {
        int zd = d - 1, zh = h - 1;
        if ((unsigned)zd < D_ && (unsigned)zh < H_) {
            const float* rb = in + zd * HW_ + zh * W_;
            for (int idx = threadIdx.x; idx < C_ * 24; idx += 224) {
                int c = idx / 24, q = idx - c * 24;
                CP_ASYNC16(sin_a + (c * INP_ + 4 + 4*q) * 4, rb + c * S_ + 4*q);
            }
            const float* wb = cw;
            for (int idx = threadIdx.x; idx < (3*C_*OCP_)/4; idx += 224)
                CP_ASYNC16(sw_a + idx * 16, wb + 4*idx);
        }
    }
    CP_COMMIT();

    #pragma unroll 1
    for (int p = 0; p < 9; ++p) {
        if (p < 8) {
            int pn = p + 1;
            int ti = pn / 3, tj = pn - 3 * ti;
            int zd = d + ti - 1, zh = h + tj - 1;
            if ((unsigned)zd < D_ && (unsigned)zh < H_) {
                int b = pn & 1;
                const float* rb = in + zd * HW_ + zh * W_;
                unsigned int din = sin_a + (b * C_ * INP_) * 4;
                for (int idx = threadIdx.x; idx < C_ * 24; idx += 224) {
                    int c = idx / 24, q = idx - c * 24;
                    CP_ASYNC16(din + (c * INP_ + 4 + 4*q) * 4, rb + c * S_ + 4*q);
                }
                const float* wb = cw + pn * 3 * (C_ * OCP_);
                unsigned int dw = sw_a + (b * 3 * C_ * OCP_) * 4;
                for (int idx = threadIdx.x; idx < (3*C_*OCP_)/4; idx += 224)
                    CP_ASYNC16(dw + idx * 16, wb + 4*idx);
            }
        }
        CP_COMMIT();
        CP_WAIT1();
        __syncthreads();

        int ti = p / 3, tj = p - 3 * ti;
        int zd = d + ti - 1, zh = h + tj - 1;
        if ((unsigned)zd < D_ && (unsigned)zh < H_) {
            const float* bin = s_in + (p & 1) * C_ * INP_;
            const float* bw  = s_w  + (p & 1) * 3 * C_ * OCP_;

            #pragma unroll 2
            for (int c = 0; c < C_; ++c) {
                const float* sr = bin + c * INP_ + 3 * vg + 3;
                u64 pv[5];
                #pragma unroll
                for (int t = 0; t < 5; ++t) { PACK2(pv[t], sr[t]); }
                #pragma unroll
                for (int tk = 0; tk < 3; ++tk) {
                    const ulonglong2* wq =
                        (const ulonglong2*)(bw + (tk * C_ + c) * OCP_ + og * 8);
                    ulonglong2 w0 = wq[0];
                    ulonglong2 w1 = wq[1];
                    #pragma unroll
                    for (int v = 0; v < 3; ++v) {
                        u64 b = pv[tk + v];
                        FFMA2(acc[v*4 + 0], w0.x, b);
                        FFMA2(acc[v*4 + 1], w0.y, b);
                        FFMA2(acc[v*4 + 2], w1.x, b);
                        FFMA2(acc[v*4 + 3], w1.y, b);
                    }
                }
            }
        }
        __syncthreads();
    }

    int sprow = (d * H_ + h) * W_ + 3 * vg;
    #pragma unroll
    for (int p = 0; p < 4; ++p) {
        int oc = og * 8 + 2 * p;
        if (oc < OC_) {
            float bx = __ldg(bias + oc);
            float by = __ldg(bias + oc + 1);
            #pragma unroll
            for (int v = 0; v < 3; ++v) {
                float2 a = unpk(acc[v*4 + p]);
                out[(oc+0) * S_ + sprow + v] = a.x + bx;
                out[(oc+1) * S_ + sprow + v] = a.y + by;
            }
        }
    }
}

// ---------------------------------------------------------------------------
// K4: Deformable conv (R11/R9 version verbatim — known best).
// ---------------------------------------------------------------------------
__global__ void __launch_bounds__(256)
deform(const float* __restrict__ in, const float* __restrict__ offs,
       const float* __restrict__ dwt, const float* __restrict__ bias,
       const float* __restrict__ resid, float* __restrict__ out) {
    __shared__ __align__(16) float ws[9 * C_ * C_];   // 36 KB
    int sp = blockIdx.x * 256 + threadIdx.x;
    int d = sp / HW_;
    int r = sp - d * HW_;
    int h = r / W_;
    int w = r - h * W_;

    u64 acc[16];
    #pragma unroll
    for (int i = 0; i < 16; i++) acc[i] = 0ull;

    #pragma unroll 1
    for (int ti = 0; ti < 3; ++ti) {
        __syncthreads();
        {
            const float4* src = (const float4*)(dwt + ti * (9 * C_ * C_));
            float4* dst = (float4*)ws;
            for (int idx = threadIdx.x; idx < 9 * C_ * C_ / 4; idx += 256)
                dst[idx] = src[idx];
        }
        __syncthreads();
        int zd = d + ti - 1;
        if ((unsigned)zd >= D_) continue;
        const float* base = in + zd * HW_;

        #pragma unroll 1
        for (int tl = 0; tl < 9; ++tl) {
            int tj = tl / 3, tk = tl - 3 * tj;
            int tap = ti * 9 + tl;

            float offh = offs[(2*tap + 0) * S_ + sp];
            float offw = offs[(2*tap + 1) * S_ + sp];
            float hp = (float)(h + tj - 1) + offh;
            float wp = (float)(w + tk - 1) + offw;
            float h0f = floorf(hp), w0f = floorf(wp);
            int h0 = (int)h0f, w0 = (int)w0f;
            float lh = hp - h0f, lw = wp - w0f;

            float m00 = ((unsigned)h0     < H_ && (unsigned)w0     < W_) ? 1.f : 0.f;
            float m01 = ((unsigned)h0     < H_ && (unsigned)(w0+1) < W_) ? 1.f : 0.f;
            float m10 = ((unsigned)(h0+1) < H_ && (unsigned)w0     < W_) ? 1.f : 0.f;
            float m11 = ((unsigned)(h0+1) < H_ && (unsigned)(w0+1) < W_) ? 1.f : 0.f;
            float w00 = (1.f - lh) * (1.f - lw) * m00;
            float w01 = (1.f - lh) * lw         * m01;
            float w10 = lh         * (1.f - lw) * m10;
            float w11 = lh         * lw         * m11;

            int h0c = min(max(h0,     0), H_ - 1);
            int h1c = min(max(h0 + 1, 0), H_ - 1);
            int w0c = min(max(w0,     0), W_ - 1);
            int w1c = min(max(w0 + 1, 0), W_ - 1);
            int i00 = h0c * W_ + w0c;
            int i01 = h0c * W_ + w1c;
            int i10 = h1c * W_ + w0c;
            int i11 = h1c * W_ + w1c;

            const float* wp_s = ws + tl * (C_ * C_);
            #pragma unroll 4
            for (int c = 0; c < C_; c++) {
                const float* pc = base + c * S_;
                float val = w00 * __ldg(pc + i00) + w01 * __ldg(pc + i01)
                          + w10 * __ldg(pc + i10) + w11 * __ldg(pc + i11);
                u64 bv; PACK2(bv, val);
                const ulonglong2* wq = (const ulonglong2*)(wp_s + c * C_);
                #pragma unroll
                for (int q = 0; q < 8; q++) {
                    ulonglong2 t = wq[q];
                    FFMA2(acc[2*q + 0], t.x, bv);
                    FFMA2(acc[2*q + 1], t.y, bv);
                }
            }
        }
    }

    if (resid) {
        #pragma unroll
        for (int q = 0; q < 16; ++q) {
            int oc = 2 * q;
            float2 a = unpk(acc[q]);
            int i0 = (oc+0) * S_ + sp, i1 = (oc+1) * S_ + sp;
            out[i0] = a.x + __ldg(bias + oc)     + __ldg(resid + i0);
            out[i1] = a.y + __ldg(bias + oc + 1) + __ldg(resid + i1);
        }
    } else {
        #pragma unroll
        for (int q = 0; q < 16; ++q) {
            int oc = 2 * q;
            float2 a = unpk(acc[q]);
            out[(oc+0) * S_ + sp] = a.x + __ldg(bias + oc);
            out[(oc+1) * S_ + sp] = a.y + __ldg(bias + oc + 1);
        }
    }
}

// ---------------------------------------------------------------------------
extern "C" void kernel_launch(void* const* d_in, const int* in_sizes, int n_in,
                              void* d_out, int out_size) {
    const float* x   = (const float*)d_in[0];
    const float* g1  = (const float*)d_in[1];
    const float* be1 = (const float*)d_in[2];
    const float* g2  = (const float*)d_in[3];
    const float* be2 = (const float*)d_in[4];
    const float* ow1 = (const float*)d_in[5];
    const float* ob1 = (const float*)d_in[6];
    const float* dw1 = (const float*)d_in[7];
    const float* db1 = (const float*)d_in[8];
    const float* ow2 = (const float*)d_in[9];
    const float* ob2 = (const float*)d_in[10];
    const float* dw2 = (const float*)d_in[11];
    const float* db2 = (const float*)d_in[12];
    float* out = (float*)d_out;

    float *ph, *pt, *poff, *pcw, *pdw;
    cudaGetSymbolAddress((void**)&ph,   g_h);
    cudaGetSymbolAddress((void**)&pt,   g_t);
    cudaGetSymbolAddress((void**)&poff, g_offb);
    cudaGetSymbolAddress((void**)&pcw,  g_cw);
    cudaGetSymbolAddress((void**)&pdw,  g_dw);

    cudaFuncSetAttribute(conv_gemm,
        cudaFuncAttributeMaxDynamicSharedMemorySize, SMEM_CONV);

    dim3 sg(STAT_BLOCKS, G_);
    const int NB_GN = TOT_ / 4 / 256;
    const int NB_SP = S_ / 256;
    dim3 gc(D_, H_);

    // pass 1 — 4 launches: stats+preps, apply+fin, conv, deform
    gn_stats_prep<<<sg, 256>>>(x, ow1, dw1);
    gn_apply_fin<<<NB_GN, 256>>>(x, g1, be1, ph);
    conv_gemm<<<gc, 224, SMEM_CONV>>>(ph, pcw, ob1, poff);
    deform<<<NB_SP, 256>>>(ph, poff, pdw, db1, nullptr, pt);

    // pass 2 (+ residual into d_out)
    gn_stats_prep<<<sg, 256>>>(pt, ow2, dw2);
    gn_apply_fin<<<NB_GN, 256>>>(pt, g2, be2, ph);
    conv_gemm<<<gc, 224, SMEM_CONV>>>(ph, pcw, ob2, poff);
    deform<<<NB_SP, 256>>>(ph, poff, pdw, db2, x, out);
}

// round 16
// speedup vs baseline: 1.5025x; 1.0721x over previous
#include <cuda_runtime.h>

// Problem constants (B=1 fixed)
#define D_   24
#define H_   96
#define W_   96
#define C_   32
#define HW_  (H_*W_)          // 9216
#define S_   (D_*HW_)         // 221184
#define TOT_ (C_*S_)          // 7077888
#define OC_  54               // offset conv output channels
#define OCP_ 56               // padded
#define G_   4
#define CPG_ (C_/G_)
#define NPG_ (CPG_*S_)
#define STAT_BLOCKS 64

typedef unsigned long long u64;

// packed f32x2 FMA: d.lo += a.lo*b.lo ; d.hi += a.hi*b.hi  (2x FP32 rate)
#define FFMA2(d, a, b) \
    asm("fma.rn.f32x2 %0, %1, %2, %0;" : "+l"(d) : "l"(a), "l"(b))
#define PACK2(d, x) \
    asm("mov.b64 %0, {%1, %1};" : "=l"(d) : "r"(__float_as_uint(x)))

#define CP_ASYNC16(dst_u32, src_ptr) \
    asm volatile("cp.async.cg.shared.global [%0], [%1], 16;" :: "r"(dst_u32), "l"(src_ptr))
#define CP_COMMIT() asm volatile("cp.async.commit_group;")
#define CP_WAIT1()  asm volatile("cp.async.wait_group 1;")

static __device__ __forceinline__ float2 unpk(u64 v) {
    unsigned int lo, hi;
    asm("mov.b64 {%0, %1}, %2;" : "=r"(lo), "=r"(hi) : "l"(v));
    float2 r; r.x = __uint_as_float(lo); r.y = __uint_as_float(hi);
    return r;
}
static __device__ __forceinline__ unsigned int smem_u32(const void* p) {
    unsigned int a;
    asm("{ .reg .u64 t; cvta.to.shared.u64 t, %1; cvt.u32.u64 %0, t; }" : "=r"(a) : "l"(p));
    return a;
}

// Scratch (device globals: allocation-free, graph-capture safe)
__device__ float g_h[TOT_];          // gn+relu output [c][s]
__device__ float g_t[TOT_];          // pass-1 result
__device__ float g_offb[OC_*S_];
__device__ float g_part[G_*STAT_BLOCKS*2];
__device__ float g_cw[27*C_*OCP_];   // transposed conv weights [tap][c][oc56]
__device__ float g_dw[27*C_*C_];     // transposed deform weights [tap][c][oc32]

// ---------------------------------------------------------------------------
// K1: GroupNorm partial stats + fused weight transposes (R15, known good).
// ---------------------------------------------------------------------------
__global__ void gn_stats_prep(const float* __restrict__ in,
                              const float* __restrict__ ow,
                              const float* __restrict__ dwi) {
    {
        int flat = (blockIdx.y * STAT_BLOCKS + blockIdx.x) * 256 + threadIdx.x;
        if (flat < 27*C_*OCP_) {
            int oc  = flat % OCP_;
            int c   = (flat / OCP_) % C_;
            int tap = flat / (OCP_*C_);
            g_cw[flat] = (oc < OC_) ? ow[(oc*C_ + c)*27 + tap] : 0.f;
        }
        if (flat < 27*C_*C_) {
            int oc  = flat & 31;
            int c   = (flat >> 5) & 31;
            int tap = flat >> 10;
            g_dw[flat] = dwi[(oc*C_ + c)*27 + tap];
        }
    }
    int g = blockIdx.y;
    const float4* p = (const float4*)(in + (size_t)g * NPG_);
    const int n4 = NPG_ / 4;
    float s = 0.f, q = 0.f;
    for (int i = blockIdx.x * blockDim.x + threadIdx.x; i < n4; i += STAT_BLOCKS * 256) {
        float4 v = p[i];
        s += v.x + v.y + v.z + v.w;
        q += v.x*v.x + v.y*v.y + v.z*v.z + v.w*v.w;
    }
    __shared__ float sh[512];
    int t = threadIdx.x;
    sh[t] = s; sh[256 + t] = q;
    __syncthreads();
    for (int o = 128; o > 0; o >>= 1) {
        if (t < o) { sh[t] += sh[t + o]; sh[256 + t] += sh[256 + t + o]; }
        __syncthreads();
    }
    if (t == 0) {
        g_part[(g*STAT_BLOCKS + blockIdx.x)*2 + 0] = sh[0];
        g_part[(g*STAT_BLOCKS + blockIdx.x)*2 + 1] = sh[256];
    }
}

// ---------------------------------------------------------------------------
// K2: gn_apply with fused final reduction (R15, known good).
// ---------------------------------------------------------------------------
__global__ void gn_apply_fin(const float* __restrict__ in, const float* __restrict__ gamma,
                             const float* __restrict__ beta, float* __restrict__ out) {
    int i4 = blockIdx.x * blockDim.x + threadIdx.x;
    int c  = i4 / (S_ / 4);
    int g  = c >> 3;

    __shared__ float red[128];
    int t = threadIdx.x;
    if (t < 64) {
        red[t]      = g_part[(g*STAT_BLOCKS + t)*2 + 0];
        red[64 + t] = g_part[(g*STAT_BLOCKS + t)*2 + 1];
    }
    __syncthreads();
    for (int o = 32; o > 0; o >>= 1) {
        if (t < o) { red[t] += red[t + o]; red[64 + t] += red[64 + t + o]; }
        __syncthreads();
    }
    float mean = red[0] / (float)NPG_;
    float var  = red[64] / (float)NPG_ - mean * mean;
    float rstd = rsqrtf(var + 1e-5f);

    float sc = rstd * gamma[c];
    float sb = beta[c] - mean * sc;
    float4 v = ((const float4*)in)[i4];
    float4 r;
    r.x = fmaxf(fmaf(v.x, sc, sb), 0.f);
    r.y = fmaxf(fmaf(v.y, sc, sb), 0.f);
    r.z = fmaxf(fmaf(v.z, sc, sb), 0.f);
    r.w = fmaxf(fmaf(v.w, sc, sb), 0.f);
    ((float4*)out)[i4] = r;
}

// ---------------------------------------------------------------------------
// K3: Offset conv, R6 tile + cp.async double-buffered staging (R11 verbatim).
// ---------------------------------------------------------------------------
#define INP_ 104
#define SMEM_CONV ((2*C_*INP_ + 2*3*C_*OCP_) * 4)    // 69632 bytes
__global__ void __launch_bounds__(224)
conv_gemm(const float* __restrict__ in, const float* __restrict__ cw,
          const float* __restrict__ bias, float* __restrict__ out) {
    extern __shared__ __align__(16) float smem[];
    float* s_in = smem;
    float* s_w  = smem + 2 * C_ * INP_;
    unsigned int sin_a = smem_u32(s_in);
    unsigned int sw_a  = smem_u32(s_w);

    int vg = threadIdx.x & 31;
    int og = threadIdx.x >> 5;
    int d  = blockIdx.x;
    int h  = blockIdx.y;

    for (int i = threadIdx.x; i < 2 * C_; i += 224) {
        s_in[i * INP_ + 3]   = 0.f;
        s_in[i * INP_ + 100] = 0.f;
    }

    u64 acc[12];
    #pragma unroll
    for (int i = 0; i < 12; i++) acc[i] = 0ull;

    {
        int zd = d - 1, zh = h - 1;
        if ((unsigned)zd < D_ && (unsigned)zh < H_) {
            const float* rb = in + zd * HW_ + zh * W_;
            for (int idx = threadIdx.x; idx < C_ * 24; idx += 224) {
                int c = idx / 24, q = idx - c * 24;
                CP_ASYNC16(sin_a + (c * INP_ + 4 + 4*q) * 4, rb + c * S_ + 4*q);
            }
            const float* wb = cw;
            for (int idx = threadIdx.x; idx < (3*C_*OCP_)/4; idx += 224)
                CP_ASYNC16(sw_a + idx * 16, wb + 4*idx);
        }
    }
    CP_COMMIT();

    #pragma unroll 1
    for (int p = 0; p < 9; ++p) {
        if (p < 8) {
            int pn = p + 1;
            int ti = pn / 3, tj = pn - 3 * ti;
            int zd = d + ti - 1, zh = h + tj - 1;
            if ((unsigned)zd < D_ && (unsigned)zh < H_) {
                int b = pn & 1;
                const float* rb = in + zd * HW_ + zh * W_;
                unsigned int din = sin_a + (b * C_ * INP_) * 4;
                for (int idx = threadIdx.x; idx < C_ * 24; idx += 224) {
                    int c = idx / 24, q = idx - c * 24;
                    CP_ASYNC16(din + (c * INP_ + 4 + 4*q) * 4, rb + c * S_ + 4*q);
                }
                const float* wb = cw + pn * 3 * (C_ * OCP_);
                unsigned int dw = sw_a + (b * 3 * C_ * OCP_) * 4;
                for (int idx = threadIdx.x; idx < (3*C_*OCP_)/4; idx += 224)
                    CP_ASYNC16(dw + idx * 16, wb + 4*idx);
            }
        }
        CP_COMMIT();
        CP_WAIT1();
        __syncthreads();

        int ti = p / 3, tj = p - 3 * ti;
        int zd = d + ti - 1, zh = h + tj - 1;
        if ((unsigned)zd < D_ && (unsigned)zh < H_) {
            const float* bin = s_in + (p & 1) * C_ * INP_;
            const float* bw  = s_w  + (p & 1) * 3 * C_ * OCP_;

            #pragma unroll 2
            for (int c = 0; c < C_; ++c) {
                const float* sr = bin + c * INP_ + 3 * vg + 3;
                u64 pv[5];
                #pragma unroll
                for (int t = 0; t < 5; ++t) { PACK2(pv[t], sr[t]); }
                #pragma unroll
                for (int tk = 0; tk < 3; ++tk) {
                    const ulonglong2* wq =
                        (const ulonglong2*)(bw + (tk * C_ + c) * OCP_ + og * 8);
                    ulonglong2 w0 = wq[0];
                    ulonglong2 w1 = wq[1];
                    #pragma unroll
                    for (int v = 0; v < 3; ++v) {
                        u64 b = pv[tk + v];
                        FFMA2(acc[v*4 + 0], w0.x, b);
                        FFMA2(acc[v*4 + 1], w0.y, b);
                        FFMA2(acc[v*4 + 2], w1.x, b);
                        FFMA2(acc[v*4 + 3], w1.y, b);
                    }
                }
            }
        }
        __syncthreads();
    }

    int sprow = (d * H_ + h) * W_ + 3 * vg;
    #pragma unroll
    for (int p = 0; p < 4; ++p) {
        int oc = og * 8 + 2 * p;
        if (oc < OC_) {
            float bx = __ldg(bias + oc);
            float by = __ldg(bias + oc + 1);
            #pragma unroll
            for (int v = 0; v < 3; ++v) {
                float2 a = unpk(acc[v*4 + p]);
                out[(oc+0) * S_ + sprow + v] = a.x + bx;
                out[(oc+1) * S_ + sprow + v] = a.y + by;
            }
        }
    }
}

// ---------------------------------------------------------------------------
// K4: Deformable conv — 2 voxels per thread (sp, sp+128), 128-thread blocks
// so ~130 live regs compile WITHOUT spills (R13's spill trap avoided).
// Weight LDS shared across both voxels: per voxel-c LSU instr 12 -> 8.
// Per-ti staging of 9 taps from pre-transposed g_dw. Grid S_/256 = 864.
// ---------------------------------------------------------------------------
__global__ void __launch_bounds__(128)
deform(const float* __restrict__ in, const float* __restrict__ offs,
       const float* __restrict__ dwt, const float* __restrict__ bias,
       const float* __restrict__ resid, float* __restrict__ out) {
    __shared__ __align__(16) float ws[9 * C_ * C_];   // 36 KB
    int sp0 = blockIdx.x * 256 + threadIdx.x;
    int sp1 = sp0 + 128;
    int d   = (blockIdx.x * 256) / HW_;               // uniform per block
    int r0  = sp0 - d * HW_;
    int h0v = r0 / W_, w0v = r0 - h0v * W_;
    int r1  = sp1 - d * HW_;
    int h1v = r1 / W_, w1v = r1 - h1v * W_;

    u64 acc[32];                     // voxel0: acc[0..15], voxel1: acc[16..31]
    #pragma unroll
    for (int i = 0; i < 32; i++) acc[i] = 0ull;

    #pragma unroll 1
    for (int ti = 0; ti < 3; ++ti) {
        __syncthreads();
        {
            const float4* src = (const float4*)(dwt + ti * (9 * C_ * C_));
            float4* dst = (float4*)ws;
            for (int idx = threadIdx.x; idx < 9 * C_ * C_ / 4; idx += 128)
                dst[idx] = src[idx];
        }
        __syncthreads();
        int zd = d + ti - 1;
        if ((unsigned)zd >= D_) continue;             // uniform per block
        const float* base = in + zd * HW_;

        #pragma unroll 1
        for (int tl = 0; tl < 9; ++tl) {              // tj*3+tk
            int tj = tl / 3, tk = tl - 3 * tj;
            int tap = ti * 9 + tl;

            float bw[2][4];
            int   bi[2][4];
            #pragma unroll
            for (int v = 0; v < 2; ++v) {
                int sp = v ? sp1 : sp0;
                int hh = v ? h1v : h0v;
                int wv = v ? w1v : w0v;
                float offh = __ldg(offs + (2*tap + 0) * S_ + sp);
                float offw = __ldg(offs + (2*tap + 1) * S_ + sp);
                float hp = (float)(hh + tj - 1) + offh;
                float wp = (float)(wv + tk - 1) + offw;
                float h0f = floorf(hp), w0f = floorf(wp);
                int h0 = (int)h0f, w0 = (int)w0f;
                float lh = hp - h0f, lw = wp - w0f;

                float m00 = ((unsigned)h0     < H_ && (unsigned)w0     < W_) ? 1.f : 0.f;
                float m01 = ((unsigned)h0     < H_ && (unsigned)(w0+1) < W_) ? 1.f : 0.f;
                float m10 = ((unsigned)(h0+1) < H_ && (unsigned)w0     < W_) ? 1.f : 0.f;
                float m11 = ((unsigned)(h0+1) < H_ && (unsigned)(w0+1) < W_) ? 1.f : 0.f;
                bw[v][0] = (1.f - lh) * (1.f - lw) * m00;
                bw[v][1] = (1.f - lh) * lw         * m01;
                bw[v][2] = lh         * (1.f - lw) * m10;
                bw[v][3] = lh         * lw         * m11;

                int h0c = min(max(h0,     0), H_ - 1);
                int h1c = min(max(h0 + 1, 0), H_ - 1);
                int w0c = min(max(w0,     0), W_ - 1);
                int w1c = min(max(w0 + 1, 0), W_ - 1);
                bi[v][0] = h0c * W_ + w0c;
                bi[v][1] = h0c * W_ + w1c;
                bi[v][2] = h1c * W_ + w0c;
                bi[v][3] = h1c * W_ + w1c;
            }

            const float* wp_s = ws + tl * (C_ * C_);
            #pragma unroll 2
            for (int c = 0; c < C_; c++) {
                const float* pc = base + c * S_;
                float val0 = bw[0][0] * __ldg(pc + bi[0][0]) + bw[0][1] * __ldg(pc + bi[0][1])
                           + bw[0][2] * __ldg(pc + bi[0][2]) + bw[0][3] * __ldg(pc + bi[0][3]);
                float val1 = bw[1][0] * __ldg(pc + bi[1][0]) + bw[1][1] * __ldg(pc + bi[1][1])
                           + bw[1][2] * __ldg(pc + bi[1][2]) + bw[1][3] * __ldg(pc + bi[1][3]);
                u64 b0, b1;
                PACK2(b0, val0); PACK2(b1, val1);
                const ulonglong2* wq = (const ulonglong2*)(wp_s + c * C_);
                #pragma unroll
                for (int q = 0; q < 8; q++) {
                    ulonglong2 t = wq[q];
                    FFMA2(acc[2*q + 0],      t.x, b0);
                    FFMA2(acc[2*q + 1],      t.y, b0);
                    FFMA2(acc[16 + 2*q + 0], t.x, b1);
                    FFMA2(acc[16 + 2*q + 1], t.y, b1);
                }
            }
        }
    }

    if (resid) {
        #pragma unroll
        for (int q = 0; q < 16; ++q) {
            int oc = 2 * q;
            float2 a0 = unpk(acc[q]);
            float2 a1 = unpk(acc[16 + q]);
            float bx = __ldg(bias + oc), by = __ldg(bias + oc + 1);
            int i00 = (oc+0)*S_ + sp0, i01 = (oc+1)*S_ + sp0;
            int i10 = (oc+0)*S_ + sp1, i11 = (oc+1)*S_ + sp1;
            out[i00] = a0.x + bx + __ldg(resid + i00);
            out[i01] = a0.y + by + __ldg(resid + i01);
            out[i10] = a1.x + bx + __ldg(resid + i10);
            out[i11] = a1.y + by + __ldg(resid + i11);
        }
    } else {
        #pragma unroll
        for (int q = 0; q < 16; ++q) {
            int oc = 2 * q;
            float2 a0 = unpk(acc[q]);
            float2 a1 = unpk(acc[16 + q]);
            float bx = __ldg(bias + oc), by = __ldg(bias + oc + 1);
            out[(oc+0)*S_ + sp0] = a0.x + bx;
            out[(oc+1)*S_ + sp0] = a0.y + by;
            out[(oc+0)*S_ + sp1] = a1.x + bx;
            out[(oc+1)*S_ + sp1] = a1.y + by;
        }
    }
}

// ---------------------------------------------------------------------------
extern "C" void kernel_launch(void* const* d_in, const int* in_sizes, int n_in,
                              void* d_out, int out_size) {
    const float* x   = (const float*)d_in[0];
    const float* g1  = (const float*)d_in[1];
    const float* be1 = (const float*)d_in[2];
    const float* g2  = (const float*)d_in[3];
    const float* be2 = (const float*)d_in[4];
    const float* ow1 = (const float*)d_in[5];
    const float* ob1 = (const float*)d_in[6];
    const float* dw1 = (const float*)d_in[7];
    const float* db1 = (const float*)d_in[8];
    const float* ow2 = (const float*)d_in[9];
    const float* ob2 = (const float*)d_in[10];
    const float* dw2 = (const float*)d_in[11];
    const float* db2 = (const float*)d_in[12];
    float* out = (float*)d_out;

    float *ph, *pt, *poff, *pcw, *pdw;
    cudaGetSymbolAddress((void**)&ph,   g_h);
    cudaGetSymbolAddress((void**)&pt,   g_t);
    cudaGetSymbolAddress((void**)&poff, g_offb);
    cudaGetSymbolAddress((void**)&pcw,  g_cw);
    cudaGetSymbolAddress((void**)&pdw,  g_dw);

    cudaFuncSetAttribute(conv_gemm,
        cudaFuncAttributeMaxDynamicSharedMemorySize, SMEM_CONV);

    dim3 sg(STAT_BLOCKS, G_);
    const int NB_GN = TOT_ / 4 / 256;
    const int NB_DF = S_ / 256;      // 864 blocks, 128 threads, 2 voxels/thread
    dim3 gc(D_, H_);

    // pass 1 — stats+preps, apply+fin, conv, deform
    gn_stats_prep<<<sg, 256>>>(x, ow1, dw1);
    gn_apply_fin<<<NB_GN, 256>>>(x, g1, be1, ph);
    conv_gemm<<<gc, 224, SMEM_CONV>>>(ph, pcw, ob1, poff);
    deform<<<NB_DF, 128>>>(ph, poff, pdw, db1, nullptr, pt);

    // pass 2 (+ residual into d_out)
    gn_stats_prep<<<sg, 256>>>(pt, ow2, dw2);
    gn_apply_fin<<<NB_GN, 256>>>(pt, g2, be2, ph);
    conv_gemm<<<gc, 224, SMEM_CONV>>>(ph, pcw, ob2, poff);
    deform<<<NB_DF, 128>>>(ph, poff, pdw, db2, x, out);
}

// round 17
// speedup vs baseline: 1.5213x; 1.0125x over previous
#include <cuda_runtime.h>

// Problem constants (B=1 fixed)
#define D_   24
#define H_   96
#define W_   96
#define C_   32
#define HW_  (H_*W_)          // 9216
#define S_   (D_*HW_)         // 221184
#define TOT_ (C_*S_)          // 7077888
#define OC_  54               // offset conv output channels
#define OCP_ 56               // padded
#define G_   4
#define CPG_ (C_/G_)
#define NPG_ (CPG_*S_)
#define STAT_BLOCKS 64

typedef unsigned long long u64;

// packed f32x2 ops (2x FP32 rate)
#define FFMA2(d, a, b) \
    asm("fma.rn.f32x2 %0, %1, %2, %0;" : "+l"(d) : "l"(a), "l"(b))
#define FFMA2_ACC(d, a, b, c0) \
    asm("fma.rn.f32x2 %0, %1, %2, %3;" : "=l"(d) : "l"(a), "l"(b), "l"(c0))
#define MUL2(d, a, b) \
    asm("mul.rn.f32x2 %0, %1, %2;" : "=l"(d) : "l"(a), "l"(b))
#define PACK2(d, x) \
    asm("mov.b64 %0, {%1, %1};" : "=l"(d) : "r"(__float_as_uint(x)))
#define PACKAB(d, lo, hi) \
    asm("mov.b64 %0, {%1, %2};" : "=l"(d) : "r"(__float_as_uint(lo)), "r"(__float_as_uint(hi)))

#define CP_ASYNC16(dst_u32, src_ptr) \
    asm volatile("cp.async.cg.shared.global [%0], [%1], 16;" :: "r"(dst_u32), "l"(src_ptr))
#define CP_COMMIT() asm volatile("cp.async.commit_group;")
#define CP_WAIT1()  asm volatile("cp.async.wait_group 1;")

static __device__ __forceinline__ float2 unpk(u64 v) {
    unsigned int lo, hi;
    asm("mov.b64 {%0, %1}, %2;" : "=r"(lo), "=r"(hi) : "l"(v));
    float2 r; r.x = __uint_as_float(lo); r.y = __uint_as_float(hi);
    return r;
}
static __device__ __forceinline__ unsigned int smem_u32(const void* p) {
    unsigned int a;
    asm("{ .reg .u64 t; cvta.to.shared.u64 t, %1; cvt.u32.u64 %0, t; }" : "=r"(a) : "l"(p));
    return a;
}

// Scratch (device globals: allocation-free, graph-capture safe)
__device__ float g_h[TOT_];          // gn+relu output [c][s]
__device__ float g_t[TOT_];          // pass-1 result
__device__ float g_offb[OC_*S_];
__device__ float g_part[G_*STAT_BLOCKS*2];
__device__ float g_cw[27*C_*OCP_];   // transposed conv weights [tap][c][oc56]
__device__ float g_dw[27*C_*C_];     // transposed deform weights [tap][c][oc32]

// ---------------------------------------------------------------------------
// K1: GroupNorm partial stats + fused weight transposes (R15, known good).
// ---------------------------------------------------------------------------
__global__ void gn_stats_prep(const float* __restrict__ in,
                              const float* __restrict__ ow,
                              const float* __restrict__ dwi) {
    {
        int flat = (blockIdx.y * STAT_BLOCKS + blockIdx.x) * 256 + threadIdx.x;
        if (flat < 27*C_*OCP_) {
            int oc  = flat % OCP_;
            int c   = (flat / OCP_) % C_;
            int tap = flat / (OCP_*C_);
            g_cw[flat] = (oc < OC_) ? ow[(oc*C_ + c)*27 + tap] : 0.f;
        }
        if (flat < 27*C_*C_) {
            int oc  = flat & 31;
            int c   = (flat >> 5) & 31;
            int tap = flat >> 10;
            g_dw[flat] = dwi[(oc*C_ + c)*27 + tap];
        }
    }
    int g = blockIdx.y;
    const float4* p = (const float4*)(in + (size_t)g * NPG_);
    const int n4 = NPG_ / 4;
    float s = 0.f, q = 0.f;
    for (int i = blockIdx.x * blockDim.x + threadIdx.x; i < n4; i += STAT_BLOCKS * 256) {
        float4 v = p[i];
        s += v.x + v.y + v.z + v.w;
        q += v.x*v.x + v.y*v.y + v.z*v.z + v.w*v.w;
    }
    __shared__ float sh[512];
    int t = threadIdx.x;
    sh[t] = s; sh[256 + t] = q;
    __syncthreads();
    for (int o = 128; o > 0; o >>= 1) {
        if (t < o) { sh[t] += sh[t + o]; sh[256 + t] += sh[256 + t + o]; }
        __syncthreads();
    }
    if (t == 0) {
        g_part[(g*STAT_BLOCKS + blockIdx.x)*2 + 0] = sh[0];
        g_part[(g*STAT_BLOCKS + blockIdx.x)*2 + 1] = sh[256];
    }
}

// ---------------------------------------------------------------------------
// K2: gn_apply with fused final reduction (R15, known good).
// ---------------------------------------------------------------------------
__global__ void gn_apply_fin(const float* __restrict__ in, const float* __restrict__ gamma,
                             const float* __restrict__ beta, float* __restrict__ out) {
    int i4 = blockIdx.x * blockDim.x + threadIdx.x;
    int c  = i4 / (S_ / 4);
    int g  = c >> 3;

    __shared__ float red[128];
    int t = threadIdx.x;
    if (t < 64) {
        red[t]      = g_part[(g*STAT_BLOCKS + t)*2 + 0];
        red[64 + t] = g_part[(g*STAT_BLOCKS + t)*2 + 1];
    }
    __syncthreads();
    for (int o = 32; o > 0; o >>= 1) {
        if (t < o) { red[t] += red[t + o]; red[64 + t] += red[64 + t + o]; }
        __syncthreads();
    }
    float mean = red[0] / (float)NPG_;
    float var  = red[64] / (float)NPG_ - mean * mean;
    float rstd = rsqrtf(var + 1e-5f);

    float sc = rstd * gamma[c];
    float sb = beta[c] - mean * sc;
    float4 v = ((const float4*)in)[i4];
    float4 r;
    r.x = fmaxf(fmaf(v.x, sc, sb), 0.f);
    r.y = fmaxf(fmaf(v.y, sc, sb), 0.f);
    r.z = fmaxf(fmaf(v.z, sc, sb), 0.f);
    r.w = fmaxf(fmaf(v.w, sc, sb), 0.f);
    ((float4*)out)[i4] = r;
}

// ---------------------------------------------------------------------------
// K3: Offset conv, R6 tile + cp.async double-buffered staging (R11 verbatim).
// ---------------------------------------------------------------------------
#define INP_ 104
#define SMEM_CONV ((2*C_*INP_ + 2*3*C_*OCP_) * 4)    // 69632 bytes
__global__ void __launch_bounds__(224)
conv_gemm(const float* __restrict__ in, const float* __restrict__ cw,
          const float* __restrict__ bias, float* __restrict__ out) {
    extern __shared__ __align__(16) float smem[];
    float* s_in = smem;
    float* s_w  = smem + 2 * C_ * INP_;
    unsigned int sin_a = smem_u32(s_in);
    unsigned int sw_a  = smem_u32(s_w);

    int vg = threadIdx.x & 31;
    int og = threadIdx.x >> 5;
    int d  = blockIdx.x;
    int h  = blockIdx.y;

    for (int i = threadIdx.x; i < 2 * C_; i += 224) {
        s_in[i * INP_ + 3]   = 0.f;
        s_in[i * INP_ + 100] = 0.f;
    }

    u64 acc[12];
    #pragma unroll
    for (int i = 0; i < 12; i++) acc[i] = 0ull;

    {
        int zd = d - 1, zh = h - 1;
        if ((unsigned)zd < D_ && (unsigned)zh < H_) {
            const float* rb = in + zd * HW_ + zh * W_;
            for (int idx = threadIdx.x; idx < C_ * 24; idx += 224) {
                int c = idx / 24, q = idx - c * 24;
                CP_ASYNC16(sin_a + (c * INP_ + 4 + 4*q) * 4, rb + c * S_ + 4*q);
            }
            const float* wb = cw;
            for (int idx = threadIdx.x; idx < (3*C_*OCP_)/4; idx += 224)
                CP_ASYNC16(sw_a + idx * 16, wb + 4*idx);
        }
    }
    CP_COMMIT();

    #pragma unroll 1
    for (int p = 0; p < 9; ++p) {
        if (p < 8) {
            int pn = p + 1;
            int ti = pn / 3, tj = pn - 3 * ti;
            int zd = d + ti - 1, zh = h + tj - 1;
            if ((unsigned)zd < D_ && (unsigned)zh < H_) {
                int b = pn & 1;
                const float* rb = in + zd * HW_ + zh * W_;
                unsigned int din = sin_a + (b * C_ * INP_) * 4;
                for (int idx = threadIdx.x; idx < C_ * 24; idx += 224) {
                    int c = idx / 24, q = idx - c * 24;
                    CP_ASYNC16(din + (c * INP_ + 4 + 4*q) * 4, rb + c * S_ + 4*q);
                }
                const float* wb = cw + pn * 3 * (C_ * OCP_);
                unsigned int dw = sw_a + (b * 3 * C_ * OCP_) * 4;
                for (int idx = threadIdx.x; idx < (3*C_*OCP_)/4; idx += 224)
                    CP_ASYNC16(dw + idx * 16, wb + 4*idx);
            }
        }
        CP_COMMIT();
        CP_WAIT1();
        __syncthreads();

        int ti = p / 3, tj = p - 3 * ti;
        int zd = d + ti - 1, zh = h + tj - 1;
        if ((unsigned)zd < D_ && (unsigned)zh < H_) {
            const float* bin = s_in + (p & 1) * C_ * INP_;
            const float* bw  = s_w  + (p & 1) * 3 * C_ * OCP_;

            #pragma unroll 2
            for (int c = 0; c < C_; ++c) {
                const float* sr = bin + c * INP_ + 3 * vg + 3;
                u64 pv[5];
                #pragma unroll
                for (int t = 0; t < 5; ++t) { PACK2(pv[t], sr[t]); }
                #pragma unroll
                for (int tk = 0; tk < 3; ++tk) {
                    const ulonglong2* wq =
                        (const ulonglong2*)(bw + (tk * C_ + c) * OCP_ + og * 8);
                    ulonglong2 w0 = wq[0];
                    ulonglong2 w1 = wq[1];
                    #pragma unroll
                    for (int v = 0; v < 3; ++v) {
                        u64 b = pv[tk + v];
                        FFMA2(acc[v*4 + 0], w0.x, b);
                        FFMA2(acc[v*4 + 1], w0.y, b);
                        FFMA2(acc[v*4 + 2], w1.x, b);
                        FFMA2(acc[v*4 + 3], w1.y, b);
                    }
                }
            }
        }
        __syncthreads();
    }

    int sprow = (d * H_ + h) * W_ + 3 * vg;
    #pragma unroll
    for (int p = 0; p < 4; ++p) {
        int oc = og * 8 + 2 * p;
        if (oc < OC_) {
            float bx = __ldg(bias + oc);
            float by = __ldg(bias + oc + 1);
            #pragma unroll
            for (int v = 0; v < 3; ++v) {
                float2 a = unpk(acc[v*4 + p]);
                out[(oc+0) * S_ + sprow + v] = a.x + bx;
                out[(oc+1) * S_ + sprow + v] = a.y + by;
            }
        }
    }
}

// ---------------------------------------------------------------------------
// K4: Deformable conv — 2 voxels/thread (R16 structure) with PACKED bilinear
// math: corners of the voxel pair packed into f32x2, weights packed per tap;
// val0/val1 computed by 1 mul.f32x2 + 3 fma.f32x2 (fma-pipe 30 -> 20 per c).
// ---------------------------------------------------------------------------
__global__ void __launch_bounds__(128)
deform(const float* __restrict__ in, const float* __restrict__ offs,
       const float* __restrict__ dwt, const float* __restrict__ bias,
       const float* __restrict__ resid, float* __restrict__ out) {
    __shared__ __align__(16) float ws[9 * C_ * C_];   // 36 KB
    int sp0 = blockIdx.x * 256 + threadIdx.x;
    int sp1 = sp0 + 128;
    int d   = (blockIdx.x * 256) / HW_;               // uniform per block
    int r0  = sp0 - d * HW_;
    int h0v = r0 / W_, w0v = r0 - h0v * W_;
    int r1  = sp1 - d * HW_;
    int h1v = r1 / W_, w1v = r1 - h1v * W_;

    u64 acc[32];                     // voxel0: acc[0..15], voxel1: acc[16..31]
    #pragma unroll
    for (int i = 0; i < 32; i++) acc[i] = 0ull;

    #pragma unroll 1
    for (int ti = 0; ti < 3; ++ti) {
        __syncthreads();
        {
            const float4* src = (const float4*)(dwt + ti * (9 * C_ * C_));
            float4* dst = (float4*)ws;
            for (int idx = threadIdx.x; idx < 9 * C_ * C_ / 4; idx += 128)
                dst[idx] = src[idx];
        }
        __syncthreads();
        int zd = d + ti - 1;
        if ((unsigned)zd >= D_) continue;             // uniform per block
        const float* base = in + zd * HW_;

        #pragma unroll 1
        for (int tl = 0; tl < 9; ++tl) {              // tj*3+tk
            int tj = tl / 3, tk = tl - 3 * tj;
            int tap = ti * 9 + tl;

            u64 bwp[4];                               // packed (bw_v0[j], bw_v1[j])
            int bi[2][4];
            {
                float bw[2][4];
                #pragma unroll
                for (int v = 0; v < 2; ++v) {
                    int sp = v ? sp1 : sp0;
                    int hh = v ? h1v : h0v;
                    int wv = v ? w1v : w0v;
                    float offh = __ldg(offs + (2*tap + 0) * S_ + sp);
                    float offw = __ldg(offs + (2*tap + 1) * S_ + sp);
                    float hp = (float)(hh + tj - 1) + offh;
                    float wp = (float)(wv + tk - 1) + offw;
                    float h0f = floorf(hp), w0f = floorf(wp);
                    int h0 = (int)h0f, w0 = (int)w0f;
                    float lh = hp - h0f, lw = wp - w0f;

                    float m00 = ((unsigned)h0     < H_ && (unsigned)w0     < W_) ? 1.f : 0.f;
                    float m01 = ((unsigned)h0     < H_ && (unsigned)(w0+1) < W_) ? 1.f : 0.f;
                    float m10 = ((unsigned)(h0+1) < H_ && (unsigned)w0     < W_) ? 1.f : 0.f;
                    float m11 = ((unsigned)(h0+1) < H_ && (unsigned)(w0+1) < W_) ? 1.f : 0.f;
                    bw[v][0] = (1.f - lh) * (1.f - lw) * m00;
                    bw[v][1] = (1.f - lh) * lw         * m01;
                    bw[v][2] = lh         * (1.f - lw) * m10;
                    bw[v][3] = lh         * lw         * m11;

                    int h0c = min(max(h0,     0), H_ - 1);
                    int h1c = min(max(h0 + 1, 0), H_ - 1);
                    int w0c = min(max(w0,     0), W_ - 1);
                    int w1c = min(max(w0 + 1, 0), W_ - 1);
                    bi[v][0] = h0c * W_ + w0c;
                    bi[v][1] = h0c * W_ + w1c;
                    bi[v][2] = h1c * W_ + w0c;
                    bi[v][3] = h1c * W_ + w1c;
                }
                #pragma unroll
                for (int j = 0; j < 4; ++j) { PACKAB(bwp[j], bw[0][j], bw[1][j]); }
            }

            const float* wp_s = ws + tl * (C_ * C_);
            #pragma unroll 2
            for (int c = 0; c < C_; c++) {
                const float* pc = base + c * S_;
                // gather 4 corners for both voxels
                float ga0 = __ldg(pc + bi[0][0]);
                float ga1 = __ldg(pc + bi[0][1]);
                float ga2 = __ldg(pc + bi[0][2]);
                float ga3 = __ldg(pc + bi[0][3]);
                float gb0 = __ldg(pc + bi[1][0]);
                float gb1 = __ldg(pc + bi[1][1]);
                float gb2 = __ldg(pc + bi[1][2]);
                float gb3 = __ldg(pc + bi[1][3]);
                // pack corner pairs and interpolate both voxels at once
                u64 gp0, gp1, gp2, gp3;
                PACKAB(gp0, ga0, gb0);
                PACKAB(gp1, ga1, gb1);
                PACKAB(gp2, ga2, gb2);
                PACKAB(gp3, ga3, gb3);
                u64 vpk;
                MUL2(vpk, gp0, bwp[0]);
                FFMA2(vpk, gp1, bwp[1]);
                FFMA2(vpk, gp2, bwp[2]);
                FFMA2(vpk, gp3, bwp[3]);
                float2 vv = unpk(vpk);
                u64 b0, b1;
                PACK2(b0, vv.x); PACK2(b1, vv.y);
                const ulonglong2* wq = (const ulonglong2*)(wp_s + c * C_);
                #pragma unroll
                for (int q = 0; q < 8; q++) {
                    ulonglong2 t = wq[q];
                    FFMA2(acc[2*q + 0],      t.x, b0);
                    FFMA2(acc[2*q + 1],      t.y, b0);
                    FFMA2(acc[16 + 2*q + 0], t.x, b1);
                    FFMA2(acc[16 + 2*q + 1], t.y, b1);
                }
            }
        }
    }

    if (resid) {
        #pragma unroll
        for (int q = 0; q < 16; ++q) {
            int oc = 2 * q;
            float2 a0 = unpk(acc[q]);
            float2 a1 = unpk(acc[16 + q]);
            float bx = __ldg(bias + oc), by = __ldg(bias + oc + 1);
            int i00 = (oc+0)*S_ + sp0, i01 = (oc+1)*S_ + sp0;
            int i10 = (oc+0)*S_ + sp1, i11 = (oc+1)*S_ + sp1;
            out[i00] = a0.x + bx + __ldg(resid + i00);
            out[i01] = a0.y + by + __ldg(resid + i01);
            out[i10] = a1.x + bx + __ldg(resid + i10);
            out[i11] = a1.y + by + __ldg(resid + i11);
        }
    } else {
        #pragma unroll
        for (int q = 0; q < 16; ++q) {
            int oc = 2 * q;
            float2 a0 = unpk(acc[q]);
            float2 a1 = unpk(acc[16 + q]);
            float bx = __ldg(bias + oc), by = __ldg(bias + oc + 1);
            out[(oc+0)*S_ + sp0] = a0.x + bx;
            out[(oc+1)*S_ + sp0] = a0.y + by;
            out[(oc+0)*S_ + sp1] = a1.x + bx;
            out[(oc+1)*S_ + sp1] = a1.y + by;
        }
    }
}

// ---------------------------------------------------------------------------
extern "C" void kernel_launch(void* const* d_in, const int* in_sizes, int n_in,
                              void* d_out, int out_size) {
    const float* x   = (const float*)d_in[0];
    const float* g1  = (const float*)d_in[1];
    const float* be1 = (const float*)d_in[2];
    const float* g2  = (const float*)d_in[3];
    const float* be2 = (const float*)d_in[4];
    const float* ow1 = (const float*)d_in[5];
    const float* ob1 = (const float*)d_in[6];
    const float* dw1 = (const float*)d_in[7];
    const float* db1 = (const float*)d_in[8];
    const float* ow2 = (const float*)d_in[9];
    const float* ob2 = (const float*)d_in[10];
    const float* dw2 = (const float*)d_in[11];
    const float* db2 = (const float*)d_in[12];
    float* out = (float*)d_out;

    float *ph, *pt, *poff, *pcw, *pdw;
    cudaGetSymbolAddress((void**)&ph,   g_h);
    cudaGetSymbolAddress((void**)&pt,   g_t);
    cudaGetSymbolAddress((void**)&poff, g_offb);
    cudaGetSymbolAddress((void**)&pcw,  g_cw);
    cudaGetSymbolAddress((void**)&pdw,  g_dw);

    cudaFuncSetAttribute(conv_gemm,
        cudaFuncAttributeMaxDynamicSharedMemorySize, SMEM_CONV);

    dim3 sg(STAT_BLOCKS, G_);
    const int NB_GN = TOT_ / 4 / 256;
    const int NB_DF = S_ / 256;      // 864 blocks, 128 threads, 2 voxels/thread
    dim3 gc(D_, H_);

    // pass 1 — stats+preps, apply+fin, conv, deform
    gn_stats_prep<<<sg, 256>>>(x, ow1, dw1);
    gn_apply_fin<<<NB_GN, 256>>>(x, g1, be1, ph);
    conv_gemm<<<gc, 224, SMEM_CONV>>>(ph, pcw, ob1, poff);
    deform<<<NB_DF, 128>>>(ph, poff, pdw, db1, nullptr, pt);

    // pass 2 (+ residual into d_out)
    gn_stats_prep<<<sg, 256>>>(pt, ow2, dw2);
    gn_apply_fin<<<NB_GN, 256>>>(pt, g2, be2, ph);
    conv_gemm<<<gc, 224, SMEM_CONV>>>(ph, pcw, ob2, poff);
    deform<<<NB_DF, 128>>>(ph, poff, pdw, db2, x, out);
}